// round 5
// baseline (speedup 1.0000x reference)
#include <cuda_runtime.h>
#include <math.h>

#define S_LEN    2048
#define D_MODEL  1024
#define N_HEADS  16
#define HEAD_DIM 64
#define BATCH    2
#define NTOK     (BATCH * S_LEN)   // 4096

// -------- scratch (device globals: no allocations allowed) --------
__device__ float g_Q[NTOK * D_MODEL];
__device__ float g_K[NTOK * D_MODEL];
__device__ float g_V[NTOK * D_MODEL];
__device__ float g_C[NTOK * D_MODEL];
__device__ float g_Xr[NTOK * D_MODEL];            // tf32-rounded x
__device__ float g_Wr[4][D_MODEL * D_MODEL];      // tf32-rounded Wq,Wk,Wv,Wo
__device__ float g_cos[S_LEN * 32];
__device__ float g_sin[S_LEN * 32];

#define LOG2E 1.4426950408889634f

__device__ __forceinline__ unsigned f2tf(float x) {
    unsigned u;
    asm("cvt.rna.tf32.f32 %0, %1;" : "=r"(u) : "f"(x));
    return u;
}
__device__ __forceinline__ float f2tff(float x) { return __uint_as_float(f2tf(x)); }

__device__ __forceinline__ void mma8(float c[4], const unsigned a[4],
                                     unsigned b0, unsigned b1) {
    asm volatile(
        "mma.sync.aligned.m16n8k8.row.col.f32.tf32.tf32.f32 "
        "{%0,%1,%2,%3},{%4,%5,%6,%7},{%8,%9},{%0,%1,%2,%3};"
        : "+f"(c[0]), "+f"(c[1]), "+f"(c[2]), "+f"(c[3])
        : "r"(a[0]), "r"(a[1]), "r"(a[2]), "r"(a[3]), "r"(b0), "r"(b1));
}

// =================================================================
// Pre-round x and the four weights to tf32-valued fp32 (one pass).
// =================================================================
__global__ void preround_kernel(const float* __restrict__ x,
                                const float* __restrict__ Wq,
                                const float* __restrict__ Wk,
                                const float* __restrict__ Wv,
                                const float* __restrict__ Wo)
{
    const int NX = NTOK * D_MODEL / 4;
    const int NW = D_MODEL * D_MODEL / 4;
    int i = blockIdx.x * blockDim.x + threadIdx.x;
    const float4* src;
    float4* dst;
    if (i < NX) { src = (const float4*)x; dst = (float4*)g_Xr; }
    else {
        int j = i - NX;
        int w = j / NW;
        i = j - w * NW;
        const float* ws[4] = {Wq, Wk, Wv, Wo};
        src = (const float4*)ws[w];
        dst = (float4*)g_Wr[w];
    }
    float4 v = src[i];
    v.x = f2tff(v.x); v.y = f2tff(v.y); v.z = f2tff(v.z); v.w = f2tff(v.w);
    dst[i] = v;
}

// =================================================================
// RoPE table (fp32 angle matching jnp, fp64 sincos)
// =================================================================
__global__ void rope_table_kernel()
{
    int i = blockIdx.x * blockDim.x + threadIdx.x;
    if (i >= S_LEN * 32) return;
    int pos = i >> 5;
    int f   = i & 31;
    float e    = (float)(2 * f) / 64.0f;
    float pw   = powf(10000.0f, e);
    float invf = 1.0f / pw;
    float angf = (float)pos * invf;
    double s, c;
    sincos((double)angf, &s, &c);
    g_cos[i] = (float)c;
    g_sin[i] = (float)s;
}

// =================================================================
// TF32 GEMM core: C[M,N] = A[M,K] @ B[N,K]^T, inputs pre-rounded.
// 128x128x16 tile, 256 thr, 3-stage cp.async.
// rope_mode: fused RoPE epilogue. round_out: emit tf32-rounded C.
// =================================================================
#define AST 20

__device__ __forceinline__ void gemm_body(
    const float* __restrict__ A, const float* __restrict__ B,
    float* __restrict__ C, int M, int N, int K,
    int mb, int nb, int rope_mode, float scale, int round_out)
{
    __shared__ __align__(16) float As[3][128 * AST];
    __shared__ __align__(16) float Bs[3][128 * AST];

    const int t    = threadIdx.x;
    const int warp = t >> 5, lane = t & 31;
    const int g    = lane >> 2, tig = lane & 3;
    const int wm   = (warp >> 2) * 64;
    const int wn   = (warp & 3) * 32;

    float acc[4][4][4];
#pragma unroll
    for (int mt = 0; mt < 4; mt++)
#pragma unroll
        for (int nt = 0; nt < 4; nt++)
#pragma unroll
            for (int i = 0; i < 4; i++) acc[mt][nt][i] = 0.f;

    const int lrow = t >> 2, lcol = (t & 3) * 4;

#define LOAD_STAGE3(buf, kt)                                                       \
    do {                                                                           \
        unsigned da = (unsigned)__cvta_generic_to_shared(                          \
            &As[buf][lrow * AST + lcol]);                                          \
        const float* ga = A + (size_t)(mb + lrow) * K + (kt) + lcol;               \
        asm volatile("cp.async.cg.shared.global [%0], [%1], 16;"                   \
                     :: "r"(da), "l"(ga));                                         \
        unsigned db = (unsigned)__cvta_generic_to_shared(                          \
            &Bs[buf][lrow * AST + lcol]);                                          \
        const float* gb = B + (size_t)(nb + lrow) * K + (kt) + lcol;               \
        asm volatile("cp.async.cg.shared.global [%0], [%1], 16;"                   \
                     :: "r"(db), "l"(gb));                                         \
        unsigned da2 = (unsigned)__cvta_generic_to_shared(                         \
            &As[buf][(lrow + 64) * AST + lcol]);                                   \
        const float* ga2 = A + (size_t)(mb + lrow + 64) * K + (kt) + lcol;         \
        asm volatile("cp.async.cg.shared.global [%0], [%1], 16;"                   \
                     :: "r"(da2), "l"(ga2));                                       \
        unsigned db2 = (unsigned)__cvta_generic_to_shared(                         \
            &Bs[buf][(lrow + 64) * AST + lcol]);                                   \
        const float* gb2 = B + (size_t)(nb + lrow + 64) * K + (kt) + lcol;         \
        asm volatile("cp.async.cg.shared.global [%0], [%1], 16;"                   \
                     :: "r"(db2), "l"(gb2));                                       \
        asm volatile("cp.async.commit_group;");                                    \
    } while (0)

    const int NIT = K / 16;
    LOAD_STAGE3(0, 0);
    LOAD_STAGE3(1, 16);

    for (int i = 0; i < NIT; i++) {
        asm volatile("cp.async.wait_group 1;");
        __syncthreads();
        if (i + 2 < NIT) {
            int nbuf = (i + 2) % 3;
            LOAD_STAGE3(nbuf, (i + 2) * 16);
        }
        const float* Ab = As[i % 3];
        const float* Bb = Bs[i % 3];

#pragma unroll
        for (int ks = 0; ks < 2; ks++) {
            const int kb = ks * 8;
            unsigned af[4][4], bf[4][2];
#pragma unroll
            for (int mt = 0; mt < 4; mt++) {
                int r0 = wm + mt * 16 + g;
                af[mt][0] = __float_as_uint(Ab[r0 * AST + kb + tig]);
                af[mt][1] = __float_as_uint(Ab[(r0 + 8) * AST + kb + tig]);
                af[mt][2] = __float_as_uint(Ab[r0 * AST + kb + tig + 4]);
                af[mt][3] = __float_as_uint(Ab[(r0 + 8) * AST + kb + tig + 4]);
            }
#pragma unroll
            for (int nt = 0; nt < 4; nt++) {
                int n0 = wn + nt * 8 + g;
                bf[nt][0] = __float_as_uint(Bb[n0 * AST + kb + tig]);
                bf[nt][1] = __float_as_uint(Bb[n0 * AST + kb + tig + 4]);
            }
#pragma unroll
            for (int mt = 0; mt < 4; mt++)
#pragma unroll
                for (int nt = 0; nt < 4; nt++)
                    mma8(acc[mt][nt], af[mt], bf[nt][0], bf[nt][1]);
        }
        __syncthreads();
    }

    // ---- epilogue (optional fused RoPE, optional tf32 rounding) ----
#pragma unroll
    for (int mt = 0; mt < 4; mt++) {
#pragma unroll
        for (int nt = 0; nt < 4; nt++) {
            int row = mb + wm + mt * 16 + g;
            int col = nb + wn + nt * 8 + 2 * tig;
            float v0 = acc[mt][nt][0], v1 = acc[mt][nt][1];
            float v2 = acc[mt][nt][2], v3 = acc[mt][nt][3];
            if (rope_mode) {
                int fi = (col & 63) >> 1;
                int p0 = row & (S_LEN - 1);
                int p1 = (row + 8) & (S_LEN - 1);
                float c0 = g_cos[p0 * 32 + fi], s0 = g_sin[p0 * 32 + fi];
                float c1 = g_cos[p1 * 32 + fi], s1 = g_sin[p1 * 32 + fi];
                float r0 = v0 * c0 - v1 * s0, r1 = v0 * s0 + v1 * c0;
                float r2 = v2 * c1 - v3 * s1, r3 = v2 * s1 + v3 * c1;
                v0 = r0 * scale; v1 = r1 * scale;
                v2 = r2 * scale; v3 = r3 * scale;
            }
            if (round_out) {
                v0 = f2tff(v0); v1 = f2tff(v1);
                v2 = f2tff(v2); v3 = f2tff(v3);
            }
            *(float2*)&C[(size_t)row * N + col] = make_float2(v0, v1);
            *(float2*)&C[(size_t)(row + 8) * N + col] = make_float2(v2, v3);
        }
    }
}

// fused QKV: grid.z selects weight/output; RoPE fused for Q (scaled) and K.
// outputs rounded to tf32 (attention consumes them as tf32 anyway).
__global__ __launch_bounds__(256, 2) void qkv_gemm_kernel(const float* __restrict__ A)
{
    const int z = blockIdx.z;
    float* outs[3] = {g_Q, g_K, g_V};
    const float* B = g_Wr[z];
    float* C = outs[z];
    int rope_mode = (z < 2) ? 1 : 0;
    float scale = (z == 0) ? 0.125f * LOG2E : 1.0f;  // fold 1/sqrt(hd) and log2(e) into Q
    gemm_body(A, B, C, NTOK, D_MODEL, D_MODEL,
              blockIdx.y * 128, blockIdx.x * 128, rope_mode, scale, 1);
}

__global__ __launch_bounds__(256, 2) void out_gemm_kernel(float* __restrict__ out)
{
    gemm_body(g_C, g_Wr[3], out, NTOK, D_MODEL, D_MODEL,
              blockIdx.y * 128, blockIdx.x * 128, 0, 1.0f, 0);
}

// =================================================================
// TF32 flash attention, causal, fragment-order smem.
// CTA: 128 q-rows, k-tiles of 64. 8 warps, warp w = rows [16w,16w+16).
// smem layout (floats):
//   [0, 8960)      : Q A-frag staging (prologue) / Ps[128][70] (mainloop)
//   [8960, 13056)  : KF  — K B-fragments, float4 per (kcp,nt,lane)
//   [13056, 17152) : VF  — V B-fragments, float4 per (kcp,nt,lane)
// Logits are in log2 units (Q pre-scaled by log2e/8): softmax uses exp2f.
// =================================================================
#define PST 70
#define KF_OFF 8960
#define VF_OFF 13056
#define ATT_SMEM3 (17152 * (int)sizeof(float))

__global__ __launch_bounds__(256, 2) void attn_tf32(
    const float* __restrict__ Q, const float* __restrict__ K,
    const float* __restrict__ V, float* __restrict__ Ctx)
{
    extern __shared__ __align__(16) float sm3[];
    float* QF = sm3;               // prologue only
    float* Ps = sm3;               // mainloop (aliases QF)
    float* KF = sm3 + KF_OFF;
    float* VF = sm3 + VF_OFF;

    const int t = threadIdx.x, warp = t >> 5, lane = t & 31;
    const int g = lane >> 2, tig = lane & 3;
    const int qb = ((int)gridDim.x - 1 - (int)blockIdx.x) * 128;  // heavy tiles first
    const int h  = blockIdx.y, b = blockIdx.z;

    const float* Qg = Q + ((size_t)b * S_LEN + qb) * D_MODEL + h * HEAD_DIM;

    // ---- stage Q (128x64, already tf32-rounded+scaled) into A-frag layout ----
#pragma unroll
    for (int i = 0; i < 8; i++) {
        int idx = t + i * 256;
        int row = idx >> 4, c4 = (idx & 15) * 4;
        float4 q4 = *(const float4*)&Qg[(size_t)row * D_MODEL + c4];
        int kcq = c4 >> 3, e4q = (c4 >> 2) & 1;
        int wr = row >> 4, gq = row & 7, hi = (row >> 3) & 1;
        float* qp = &QF[(((kcq << 3) + wr) * 32 + gq * 4) * 4 + hi + (e4q << 1)];
        qp[0] = q4.x; qp[4] = q4.y; qp[8] = q4.z; qp[12] = q4.w;
    }
    __syncthreads();

    unsigned qf[8][4];
#pragma unroll
    for (int kc = 0; kc < 8; kc++) {
        float4 qv = *(const float4*)&QF[((kc * 8 + warp) * 32 + lane) * 4];
        qf[kc][0] = __float_as_uint(qv.x);
        qf[kc][1] = __float_as_uint(qv.y);
        qf[kc][2] = __float_as_uint(qv.z);
        qf[kc][3] = __float_as_uint(qv.w);
    }

    float m0 = -1e30f, m1 = -1e30f, l0 = 0.f, l1 = 0.f;
    float o[8][4];
#pragma unroll
    for (int nt = 0; nt < 8; nt++)
#pragma unroll
        for (int i = 0; i < 4; i++) o[nt][i] = 0.f;

    const int r0 = qb + warp * 16 + g;
    const int r1 = r0 + 8;
    const int wrow_max = qb + warp * 16 + 15;

    for (int kt = 0; kt <= qb + 64; kt += 64) {
        __syncthreads();   // prev-iter KF/VF/Ps reads complete (also guards QF alias)
        const float* Kg = K + ((size_t)b * S_LEN + kt) * D_MODEL + h * HEAD_DIM;
        const float* Vg = V + ((size_t)b * S_LEN + kt) * D_MODEL + h * HEAD_DIM;
#pragma unroll
        for (int i = 0; i < 4; i++) {
            int idx = t + i * 256;
            int row = idx >> 4, c4 = (idx & 15) * 4;   // row=token, c4=dim
            float4 k4 = *(const float4*)&Kg[(size_t)row * D_MODEL + c4];
            float4 v4 = *(const float4*)&Vg[(size_t)row * D_MODEL + c4];
            // K scatter: B-frag (kcp, nt=token/8, lane=(token%8)*4+m, e=(dim%16)/4)
            int kcp = c4 >> 4, eK = (c4 >> 2) & 3, nt = row >> 3, Lb = (row & 7) * 4;
            float* kp = &KF[(((kcp << 3) + nt) * 32 + Lb) * 4 + eK];
            kp[0] = k4.x; kp[4] = k4.y; kp[8] = k4.z; kp[12] = k4.w;
            // V scatter: B-frag (kcp=token/16, nt=dim/8, lane=(dim%8)*4+token%4, e=(token%16)/4)
            int kcpv = row >> 4, eV = (row >> 2) & 3, tigv = row & 3;
            int ntv = c4 >> 3, gb = c4 & 7;
            float* vp = &VF[(((kcpv << 3) + ntv) * 32 + gb * 4 + tigv) * 4 + eV];
            vp[0] = v4.x; vp[16] = v4.y; vp[32] = v4.z; vp[48] = v4.w;
        }
        __syncthreads();

        if (kt > wrow_max) continue;

        // ---- S = Q K^T (B-frags via LDS.128) ----
        float s[8][4];
#pragma unroll
        for (int nt = 0; nt < 8; nt++) {
            float c[4] = {0.f, 0.f, 0.f, 0.f};
#pragma unroll
            for (int kcp = 0; kcp < 4; kcp++) {
                float4 bb = *(const float4*)&KF[((kcp * 8 + nt) * 32 + lane) * 4];
                mma8(c, qf[2 * kcp],     __float_as_uint(bb.x), __float_as_uint(bb.y));
                mma8(c, qf[2 * kcp + 1], __float_as_uint(bb.z), __float_as_uint(bb.w));
            }
            s[nt][0] = c[0]; s[nt][1] = c[1]; s[nt][2] = c[2]; s[nt][3] = c[3];
        }

        // ---- causal mask (diagonal tiles only) ----
        if (kt + 63 > qb + warp * 16) {
#pragma unroll
            for (int nt = 0; nt < 8; nt++) {
                int k0 = kt + nt * 8 + 2 * tig;
                if (k0 > r0)     s[nt][0] = -1e30f;
                if (k0 + 1 > r0) s[nt][1] = -1e30f;
                if (k0 > r1)     s[nt][2] = -1e30f;
                if (k0 + 1 > r1) s[nt][3] = -1e30f;
            }
        }

        // ---- online softmax (log2 domain) ----
        float mx0 = -1e30f, mx1 = -1e30f;
#pragma unroll
        for (int nt = 0; nt < 8; nt++) {
            mx0 = fmaxf(mx0, fmaxf(s[nt][0], s[nt][1]));
            mx1 = fmaxf(mx1, fmaxf(s[nt][2], s[nt][3]));
        }
        mx0 = fmaxf(mx0, __shfl_xor_sync(0xffffffffu, mx0, 1));
        mx0 = fmaxf(mx0, __shfl_xor_sync(0xffffffffu, mx0, 2));
        mx1 = fmaxf(mx1, __shfl_xor_sync(0xffffffffu, mx1, 1));
        mx1 = fmaxf(mx1, __shfl_xor_sync(0xffffffffu, mx1, 2));

        float nm0 = fmaxf(m0, mx0), nm1 = fmaxf(m1, mx1);
        float a0 = exp2f(m0 - nm0), a1 = exp2f(m1 - nm1);
        float sum0 = 0.f, sum1 = 0.f;
#pragma unroll
        for (int nt = 0; nt < 8; nt++) {
            s[nt][0] = exp2f(s[nt][0] - nm0);
            s[nt][1] = exp2f(s[nt][1] - nm0);
            s[nt][2] = exp2f(s[nt][2] - nm1);
            s[nt][3] = exp2f(s[nt][3] - nm1);
            sum0 += s[nt][0] + s[nt][1];
            sum1 += s[nt][2] + s[nt][3];
        }
        sum0 += __shfl_xor_sync(0xffffffffu, sum0, 1);
        sum0 += __shfl_xor_sync(0xffffffffu, sum0, 2);
        sum1 += __shfl_xor_sync(0xffffffffu, sum1, 1);
        sum1 += __shfl_xor_sync(0xffffffffu, sum1, 2);

        l0 = l0 * a0 + sum0;
        l1 = l1 * a1 + sum1;
        m0 = nm0; m1 = nm1;
#pragma unroll
        for (int nt = 0; nt < 8; nt++) {
            o[nt][0] *= a0; o[nt][1] *= a0;
            o[nt][2] *= a1; o[nt][3] *= a1;
        }

        // ---- P (tf32) to warp-private Ps rows ----
#pragma unroll
        for (int nt = 0; nt < 8; nt++) {
            *(float2*)&Ps[(warp * 16 + g) * PST + nt * 8 + 2 * tig] =
                make_float2(f2tff(s[nt][0]), f2tff(s[nt][1]));
            *(float2*)&Ps[(warp * 16 + g + 8) * PST + nt * 8 + 2 * tig] =
                make_float2(f2tff(s[nt][2]), f2tff(s[nt][3]));
        }
        __syncwarp();

        // ---- O += P @ V (V B-frags via LDS.128) ----
#pragma unroll
        for (int kcp = 0; kcp < 4; kcp++) {
            unsigned pf0[4], pf1[4];
            pf0[0] = __float_as_uint(Ps[(warp * 16 + g) * PST + kcp * 16 + tig]);
            pf0[1] = __float_as_uint(Ps[(warp * 16 + g + 8) * PST + kcp * 16 + tig]);
            pf0[2] = __float_as_uint(Ps[(warp * 16 + g) * PST + kcp * 16 + tig + 4]);
            pf0[3] = __float_as_uint(Ps[(warp * 16 + g + 8) * PST + kcp * 16 + tig + 4]);
            pf1[0] = __float_as_uint(Ps[(warp * 16 + g) * PST + kcp * 16 + 8 + tig]);
            pf1[1] = __float_as_uint(Ps[(warp * 16 + g + 8) * PST + kcp * 16 + 8 + tig]);
            pf1[2] = __float_as_uint(Ps[(warp * 16 + g) * PST + kcp * 16 + 12 + tig]);
            pf1[3] = __float_as_uint(Ps[(warp * 16 + g + 8) * PST + kcp * 16 + 12 + tig]);
#pragma unroll
            for (int nt = 0; nt < 8; nt++) {
                float4 vv = *(const float4*)&VF[((kcp * 8 + nt) * 32 + lane) * 4];
                mma8(o[nt], pf0, __float_as_uint(vv.x), __float_as_uint(vv.y));
                mma8(o[nt], pf1, __float_as_uint(vv.z), __float_as_uint(vv.w));
            }
        }
        __syncwarp();
    }

    // ---- epilogue: normalize, round to tf32 (next GEMM input), store ----
    float inv0 = 1.0f / l0, inv1 = 1.0f / l1;
    float* Cb = Ctx + ((size_t)b * S_LEN + qb + warp * 16) * D_MODEL + h * HEAD_DIM;
#pragma unroll
    for (int nt = 0; nt < 8; nt++) {
        *(float2*)&Cb[(size_t)g * D_MODEL + nt * 8 + 2 * tig] =
            make_float2(f2tff(o[nt][0] * inv0), f2tff(o[nt][1] * inv0));
        *(float2*)&Cb[(size_t)(g + 8) * D_MODEL + nt * 8 + 2 * tig] =
            make_float2(f2tff(o[nt][2] * inv1), f2tff(o[nt][3] * inv1));
    }
}

// =================================================================
// Launch
// =================================================================
extern "C" void kernel_launch(void* const* d_in, const int* in_sizes, int n_in,
                              void* d_out, int out_size)
{
    const float* x  = (const float*)d_in[0];
    const float* Wq = (const float*)d_in[1];
    const float* Wk = (const float*)d_in[2];
    const float* Wv = (const float*)d_in[3];
    const float* Wo = (const float*)d_in[4];
    float* out = (float*)d_out;

    float *Q, *K, *V, *C, *Xr;
    cudaGetSymbolAddress((void**)&Q, g_Q);
    cudaGetSymbolAddress((void**)&K, g_K);
    cudaGetSymbolAddress((void**)&V, g_V);
    cudaGetSymbolAddress((void**)&C, g_C);
    cudaGetSymbolAddress((void**)&Xr, g_Xr);

    // 0: rope table
    rope_table_kernel<<<(S_LEN * 32 + 255) / 256, 256>>>();

    // 1: pre-round x + weights
    int nr4 = (NTOK * D_MODEL + 4 * D_MODEL * D_MODEL) / 4;
    preround_kernel<<<(nr4 + 255) / 256, 256>>>(x, Wq, Wk, Wv, Wo);

    // 2: fused QKV projections + RoPE epilogue (tf32-rounded outputs)
    qkv_gemm_kernel<<<dim3(D_MODEL / 128, NTOK / 128, 3), 256>>>(Xr);

    // 3: attention
    cudaFuncSetAttribute(attn_tf32, cudaFuncAttributeMaxDynamicSharedMemorySize, ATT_SMEM3);
    attn_tf32<<<dim3(S_LEN / 128, N_HEADS, BATCH), 256, ATT_SMEM3>>>(Q, K, V, C);

    // 4: output projection
    out_gemm_kernel<<<dim3(D_MODEL / 128, NTOK / 128), 256>>>(out);
}

// round 6
// speedup vs baseline: 1.1615x; 1.1615x over previous
#include <cuda_runtime.h>
#include <math.h>

#define S_LEN    2048
#define D_MODEL  1024
#define N_HEADS  16
#define HEAD_DIM 64
#define BATCH    2
#define NTOK     (BATCH * S_LEN)   // 4096

// -------- scratch (device globals: no allocations allowed) --------
__device__ float g_Q[NTOK * D_MODEL];
__device__ float g_K[NTOK * D_MODEL];
__device__ float g_V[NTOK * D_MODEL];
__device__ float g_C[NTOK * D_MODEL];
__device__ float g_Xr[NTOK * D_MODEL];            // tf32-rounded x
__device__ float g_Wr[4][D_MODEL * D_MODEL];      // tf32-rounded Wq,Wk,Wv,Wo
__device__ float g_cos[S_LEN * 32];
__device__ float g_sin[S_LEN * 32];

#define LOG2E 1.4426950408889634f

__device__ __forceinline__ unsigned f2tf(float x) {
    unsigned u;
    asm("cvt.rna.tf32.f32 %0, %1;" : "=r"(u) : "f"(x));
    return u;
}
__device__ __forceinline__ float f2tff(float x) { return __uint_as_float(f2tf(x)); }

__device__ __forceinline__ void mma8(float c[4], const unsigned a[4],
                                     unsigned b0, unsigned b1) {
    asm volatile(
        "mma.sync.aligned.m16n8k8.row.col.f32.tf32.tf32.f32 "
        "{%0,%1,%2,%3},{%4,%5,%6,%7},{%8,%9},{%0,%1,%2,%3};"
        : "+f"(c[0]), "+f"(c[1]), "+f"(c[2]), "+f"(c[3])
        : "r"(a[0]), "r"(a[1]), "r"(a[2]), "r"(a[3]), "r"(b0), "r"(b1));
}

// =================================================================
// Pre-round x and the four weights to tf32-valued fp32 (one pass).
// =================================================================
__global__ void preround_kernel(const float* __restrict__ x,
                                const float* __restrict__ Wq,
                                const float* __restrict__ Wk,
                                const float* __restrict__ Wv,
                                const float* __restrict__ Wo)
{
    const int NX = NTOK * D_MODEL / 4;
    const int NW = D_MODEL * D_MODEL / 4;
    int i = blockIdx.x * blockDim.x + threadIdx.x;
    const float4* src;
    float4* dst;
    if (i < NX) { src = (const float4*)x; dst = (float4*)g_Xr; }
    else {
        int j = i - NX;
        int w = j / NW;
        i = j - w * NW;
        const float* ws[4] = {Wq, Wk, Wv, Wo};
        src = (const float4*)ws[w];
        dst = (float4*)g_Wr[w];
    }
    float4 v = src[i];
    v.x = f2tff(v.x); v.y = f2tff(v.y); v.z = f2tff(v.z); v.w = f2tff(v.w);
    dst[i] = v;
}

// =================================================================
// RoPE table (fp32 angle matching jnp, fp64 sincos)
// =================================================================
__global__ void rope_table_kernel()
{
    int i = blockIdx.x * blockDim.x + threadIdx.x;
    if (i >= S_LEN * 32) return;
    int pos = i >> 5;
    int f   = i & 31;
    float e    = (float)(2 * f) / 64.0f;
    float pw   = powf(10000.0f, e);
    float invf = 1.0f / pw;
    float angf = (float)pos * invf;
    double s, c;
    sincos((double)angf, &s, &c);
    g_cos[i] = (float)c;
    g_sin[i] = (float)s;
}

// =================================================================
// TF32 GEMM core: C[M,N] = A[M,K] @ B[N,K]^T, inputs pre-rounded.
// 128x128x16 tile, 256 thr, 3-stage cp.async, ONE sync per iter.
// =================================================================
#define AST 20

__device__ __forceinline__ void gemm_body(
    const float* __restrict__ A, const float* __restrict__ B,
    float* __restrict__ C, int M, int N, int K,
    int mb, int nb, int rope_mode, float scale, int round_out)
{
    __shared__ __align__(16) float As[3][128 * AST];
    __shared__ __align__(16) float Bs[3][128 * AST];

    const int t    = threadIdx.x;
    const int warp = t >> 5, lane = t & 31;
    const int g    = lane >> 2, tig = lane & 3;
    const int wm   = (warp >> 2) * 64;
    const int wn   = (warp & 3) * 32;

    float acc[4][4][4];
#pragma unroll
    for (int mt = 0; mt < 4; mt++)
#pragma unroll
        for (int nt = 0; nt < 4; nt++)
#pragma unroll
            for (int i = 0; i < 4; i++) acc[mt][nt][i] = 0.f;

    const int lrow = t >> 2, lcol = (t & 3) * 4;

#define LOAD_STAGE3(buf, kt)                                                       \
    do {                                                                           \
        unsigned da = (unsigned)__cvta_generic_to_shared(                          \
            &As[buf][lrow * AST + lcol]);                                          \
        const float* ga = A + (size_t)(mb + lrow) * K + (kt) + lcol;               \
        asm volatile("cp.async.cg.shared.global [%0], [%1], 16;"                   \
                     :: "r"(da), "l"(ga));                                         \
        unsigned db = (unsigned)__cvta_generic_to_shared(                          \
            &Bs[buf][lrow * AST + lcol]);                                          \
        const float* gb = B + (size_t)(nb + lrow) * K + (kt) + lcol;               \
        asm volatile("cp.async.cg.shared.global [%0], [%1], 16;"                   \
                     :: "r"(db), "l"(gb));                                         \
        unsigned da2 = (unsigned)__cvta_generic_to_shared(                         \
            &As[buf][(lrow + 64) * AST + lcol]);                                   \
        const float* ga2 = A + (size_t)(mb + lrow + 64) * K + (kt) + lcol;         \
        asm volatile("cp.async.cg.shared.global [%0], [%1], 16;"                   \
                     :: "r"(da2), "l"(ga2));                                       \
        unsigned db2 = (unsigned)__cvta_generic_to_shared(                         \
            &Bs[buf][(lrow + 64) * AST + lcol]);                                   \
        const float* gb2 = B + (size_t)(nb + lrow + 64) * K + (kt) + lcol;         \
        asm volatile("cp.async.cg.shared.global [%0], [%1], 16;"                   \
                     :: "r"(db2), "l"(gb2));                                       \
        asm volatile("cp.async.commit_group;");                                    \
    } while (0)

    const int NIT = K / 16;
    LOAD_STAGE3(0, 0);
    LOAD_STAGE3(1, 16);

    for (int i = 0; i < NIT; i++) {
        asm volatile("cp.async.wait_group 1;");
        __syncthreads();
        // Safe single-sync 3-stage: all warps finished reading buf (i-1)%3
        // before this barrier, and stage i+2 writes exactly that buffer.
        if (i + 2 < NIT) {
            int nbuf = (i + 2) % 3;
            LOAD_STAGE3(nbuf, (i + 2) * 16);
        }
        const float* Ab = As[i % 3];
        const float* Bb = Bs[i % 3];

#pragma unroll
        for (int ks = 0; ks < 2; ks++) {
            const int kb = ks * 8;
            unsigned af[4][4], bf[4][2];
#pragma unroll
            for (int mt = 0; mt < 4; mt++) {
                int r0 = wm + mt * 16 + g;
                af[mt][0] = __float_as_uint(Ab[r0 * AST + kb + tig]);
                af[mt][1] = __float_as_uint(Ab[(r0 + 8) * AST + kb + tig]);
                af[mt][2] = __float_as_uint(Ab[r0 * AST + kb + tig + 4]);
                af[mt][3] = __float_as_uint(Ab[(r0 + 8) * AST + kb + tig + 4]);
            }
#pragma unroll
            for (int nt = 0; nt < 4; nt++) {
                int n0 = wn + nt * 8 + g;
                bf[nt][0] = __float_as_uint(Bb[n0 * AST + kb + tig]);
                bf[nt][1] = __float_as_uint(Bb[n0 * AST + kb + tig + 4]);
            }
#pragma unroll
            for (int mt = 0; mt < 4; mt++)
#pragma unroll
                for (int nt = 0; nt < 4; nt++)
                    mma8(acc[mt][nt], af[mt], bf[nt][0], bf[nt][1]);
        }
    }

    // ---- epilogue (optional fused RoPE, optional tf32 rounding) ----
#pragma unroll
    for (int mt = 0; mt < 4; mt++) {
#pragma unroll
        for (int nt = 0; nt < 4; nt++) {
            int row = mb + wm + mt * 16 + g;
            int col = nb + wn + nt * 8 + 2 * tig;
            float v0 = acc[mt][nt][0], v1 = acc[mt][nt][1];
            float v2 = acc[mt][nt][2], v3 = acc[mt][nt][3];
            if (rope_mode) {
                int fi = (col & 63) >> 1;
                int p0 = row & (S_LEN - 1);
                int p1 = (row + 8) & (S_LEN - 1);
                float c0 = g_cos[p0 * 32 + fi], s0 = g_sin[p0 * 32 + fi];
                float c1 = g_cos[p1 * 32 + fi], s1 = g_sin[p1 * 32 + fi];
                float r0 = v0 * c0 - v1 * s0, r1 = v0 * s0 + v1 * c0;
                float r2 = v2 * c1 - v3 * s1, r3 = v2 * s1 + v3 * c1;
                v0 = r0 * scale; v1 = r1 * scale;
                v2 = r2 * scale; v3 = r3 * scale;
            }
            if (round_out) {
                v0 = f2tff(v0); v1 = f2tff(v1);
                v2 = f2tff(v2); v3 = f2tff(v3);
            }
            *(float2*)&C[(size_t)row * N + col] = make_float2(v0, v1);
            *(float2*)&C[(size_t)(row + 8) * N + col] = make_float2(v2, v3);
        }
    }
}

// fused QKV: grid.z selects weight/output; RoPE fused for Q (scaled) and K.
// outputs rounded to tf32 (attention consumes them as tf32 anyway).
__global__ __launch_bounds__(256, 2) void qkv_gemm_kernel(const float* __restrict__ A)
{
    const int z = blockIdx.z;
    float* outs[3] = {g_Q, g_K, g_V};
    const float* B = g_Wr[z];
    float* C = outs[z];
    int rope_mode = (z < 2) ? 1 : 0;
    float scale = (z == 0) ? 0.125f * LOG2E : 1.0f;  // fold 1/sqrt(hd) + log2e into Q
    gemm_body(A, B, C, NTOK, D_MODEL, D_MODEL,
              blockIdx.y * 128, blockIdx.x * 128, rope_mode, scale, 1);
}

__global__ __launch_bounds__(256, 2) void out_gemm_kernel(float* __restrict__ out)
{
    gemm_body(g_C, g_Wr[3], out, NTOK, D_MODEL, D_MODEL,
              blockIdx.y * 128, blockIdx.x * 128, 0, 1.0f, 0);
}

// =================================================================
// TF32 flash attention, causal — R4 structure (row-major smem, 220us),
// staging without cvt (inputs pre-rounded), exp2f softmax, heavy-first.
// =================================================================
#define ST 72
#define ATT_SMEM2 ((64 * ST + 64 * ST + 128 * ST) * (int)sizeof(float))

__global__ __launch_bounds__(256, 2) void attn_tf32(
    const float* __restrict__ Q, const float* __restrict__ K,
    const float* __restrict__ V, float* __restrict__ Ctx)
{
    extern __shared__ __align__(16) float sm2[];
    float* Ks = sm2;
    float* Vs = sm2 + 64 * ST;
    float* Ps = sm2 + 128 * ST;

    const int t = threadIdx.x, warp = t >> 5, lane = t & 31;
    const int g = lane >> 2, tig = lane & 3;
    const int qb = ((int)gridDim.x - 1 - (int)blockIdx.x) * 128;  // heavy tiles first
    const int h  = blockIdx.y, b = blockIdx.z;

    const float* Qg = Q + ((size_t)b * S_LEN + qb) * D_MODEL + h * HEAD_DIM;

    // ---- stage Q (pre-rounded) into Ps rows, then pick up A-fragments ----
#pragma unroll
    for (int i = 0; i < 8; i++) {
        int idx = t + i * 256;
        int row = idx >> 4, c4 = (idx & 15) * 4;
        *(float4*)&Ps[row * ST + c4] =
            *(const float4*)&Qg[(size_t)row * D_MODEL + c4];
    }
    __syncthreads();

    unsigned qf[8][4];
#pragma unroll
    for (int kc = 0; kc < 8; kc++) {
        qf[kc][0] = __float_as_uint(Ps[(warp * 16 + g) * ST + kc * 8 + tig]);
        qf[kc][1] = __float_as_uint(Ps[(warp * 16 + g + 8) * ST + kc * 8 + tig]);
        qf[kc][2] = __float_as_uint(Ps[(warp * 16 + g) * ST + kc * 8 + tig + 4]);
        qf[kc][3] = __float_as_uint(Ps[(warp * 16 + g + 8) * ST + kc * 8 + tig + 4]);
    }

    float m0 = -1e30f, m1 = -1e30f, l0 = 0.f, l1 = 0.f;
    float o[8][4];
#pragma unroll
    for (int nt = 0; nt < 8; nt++)
#pragma unroll
        for (int i = 0; i < 4; i++) o[nt][i] = 0.f;

    const int r0 = qb + warp * 16 + g;
    const int r1 = r0 + 8;
    const int wrow_max = qb + warp * 16 + 15;

    for (int kt = 0; kt <= qb + 64; kt += 64) {
        __syncthreads();   // prev-iter Ks/Vs/Ps reads complete
        const float* Kg = K + ((size_t)b * S_LEN + kt) * D_MODEL + h * HEAD_DIM;
        const float* Vg = V + ((size_t)b * S_LEN + kt) * D_MODEL + h * HEAD_DIM;
#pragma unroll
        for (int i = 0; i < 4; i++) {
            int idx = t + i * 256;
            int row = idx >> 4, c4 = (idx & 15) * 4;
            *(float4*)&Ks[row * ST + c4] =
                *(const float4*)&Kg[(size_t)row * D_MODEL + c4];
            *(float4*)&Vs[row * ST + c4] =
                *(const float4*)&Vg[(size_t)row * D_MODEL + c4];
        }
        __syncthreads();

        if (kt > wrow_max) continue;

        // ---- S = Q K^T ----
        float s[8][4];
#pragma unroll
        for (int nt = 0; nt < 8; nt++) {
            float c[4] = {0.f, 0.f, 0.f, 0.f};
#pragma unroll
            for (int kc = 0; kc < 8; kc++) {
                unsigned b0 = __float_as_uint(Ks[(nt * 8 + g) * ST + kc * 8 + tig]);
                unsigned b1 = __float_as_uint(Ks[(nt * 8 + g) * ST + kc * 8 + tig + 4]);
                mma8(c, qf[kc], b0, b1);
            }
            s[nt][0] = c[0]; s[nt][1] = c[1]; s[nt][2] = c[2]; s[nt][3] = c[3];
        }

        // ---- causal mask (diagonal tiles only) ----
        if (kt + 63 > qb + warp * 16) {
#pragma unroll
            for (int nt = 0; nt < 8; nt++) {
                int k0 = kt + nt * 8 + 2 * tig;
                if (k0 > r0)     s[nt][0] = -1e30f;
                if (k0 + 1 > r0) s[nt][1] = -1e30f;
                if (k0 > r1)     s[nt][2] = -1e30f;
                if (k0 + 1 > r1) s[nt][3] = -1e30f;
            }
        }

        // ---- online softmax (log2 domain) ----
        float mx0 = -1e30f, mx1 = -1e30f;
#pragma unroll
        for (int nt = 0; nt < 8; nt++) {
            mx0 = fmaxf(mx0, fmaxf(s[nt][0], s[nt][1]));
            mx1 = fmaxf(mx1, fmaxf(s[nt][2], s[nt][3]));
        }
        mx0 = fmaxf(mx0, __shfl_xor_sync(0xffffffffu, mx0, 1));
        mx0 = fmaxf(mx0, __shfl_xor_sync(0xffffffffu, mx0, 2));
        mx1 = fmaxf(mx1, __shfl_xor_sync(0xffffffffu, mx1, 1));
        mx1 = fmaxf(mx1, __shfl_xor_sync(0xffffffffu, mx1, 2));

        float nm0 = fmaxf(m0, mx0), nm1 = fmaxf(m1, mx1);
        float a0 = exp2f(m0 - nm0), a1 = exp2f(m1 - nm1);
        float sum0 = 0.f, sum1 = 0.f;
#pragma unroll
        for (int nt = 0; nt < 8; nt++) {
            s[nt][0] = exp2f(s[nt][0] - nm0);
            s[nt][1] = exp2f(s[nt][1] - nm0);
            s[nt][2] = exp2f(s[nt][2] - nm1);
            s[nt][3] = exp2f(s[nt][3] - nm1);
            sum0 += s[nt][0] + s[nt][1];
            sum1 += s[nt][2] + s[nt][3];
        }
        sum0 += __shfl_xor_sync(0xffffffffu, sum0, 1);
        sum0 += __shfl_xor_sync(0xffffffffu, sum0, 2);
        sum1 += __shfl_xor_sync(0xffffffffu, sum1, 1);
        sum1 += __shfl_xor_sync(0xffffffffu, sum1, 2);

        l0 = l0 * a0 + sum0;
        l1 = l1 * a1 + sum1;
        m0 = nm0; m1 = nm1;
#pragma unroll
        for (int nt = 0; nt < 8; nt++) {
            o[nt][0] *= a0; o[nt][1] *= a0;
            o[nt][2] *= a1; o[nt][3] *= a1;
        }

        // ---- P (tf32) to warp-private Ps rows ----
#pragma unroll
        for (int nt = 0; nt < 8; nt++) {
            *(float2*)&Ps[(warp * 16 + g) * ST + nt * 8 + 2 * tig] =
                make_float2(f2tff(s[nt][0]), f2tff(s[nt][1]));
            *(float2*)&Ps[(warp * 16 + g + 8) * ST + nt * 8 + 2 * tig] =
                make_float2(f2tff(s[nt][2]), f2tff(s[nt][3]));
        }
        __syncwarp();

        // ---- O += P @ V ----
#pragma unroll
        for (int kc = 0; kc < 8; kc++) {
            unsigned pf[4];
            pf[0] = __float_as_uint(Ps[(warp * 16 + g) * ST + kc * 8 + tig]);
            pf[1] = __float_as_uint(Ps[(warp * 16 + g + 8) * ST + kc * 8 + tig]);
            pf[2] = __float_as_uint(Ps[(warp * 16 + g) * ST + kc * 8 + tig + 4]);
            pf[3] = __float_as_uint(Ps[(warp * 16 + g + 8) * ST + kc * 8 + tig + 4]);
#pragma unroll
            for (int nt = 0; nt < 8; nt++) {
                unsigned b0 = __float_as_uint(Vs[(kc * 8 + tig) * ST + nt * 8 + g]);
                unsigned b1 = __float_as_uint(Vs[(kc * 8 + tig + 4) * ST + nt * 8 + g]);
                mma8(o[nt], pf, b0, b1);
            }
        }
        __syncwarp();
    }

    // ---- epilogue: normalize, round to tf32 (next GEMM input), store ----
    float inv0 = 1.0f / l0, inv1 = 1.0f / l1;
    float* Cb = Ctx + ((size_t)b * S_LEN + qb + warp * 16) * D_MODEL + h * HEAD_DIM;
#pragma unroll
    for (int nt = 0; nt < 8; nt++) {
        *(float2*)&Cb[(size_t)g * D_MODEL + nt * 8 + 2 * tig] =
            make_float2(f2tff(o[nt][0] * inv0), f2tff(o[nt][1] * inv0));
        *(float2*)&Cb[(size_t)(g + 8) * D_MODEL + nt * 8 + 2 * tig] =
            make_float2(f2tff(o[nt][2] * inv1), f2tff(o[nt][3] * inv1));
    }
}

// =================================================================
// Launch
// =================================================================
extern "C" void kernel_launch(void* const* d_in, const int* in_sizes, int n_in,
                              void* d_out, int out_size)
{
    const float* x  = (const float*)d_in[0];
    const float* Wq = (const float*)d_in[1];
    const float* Wk = (const float*)d_in[2];
    const float* Wv = (const float*)d_in[3];
    const float* Wo = (const float*)d_in[4];
    float* out = (float*)d_out;

    float *Q, *K, *V, *C, *Xr;
    cudaGetSymbolAddress((void**)&Q, g_Q);
    cudaGetSymbolAddress((void**)&K, g_K);
    cudaGetSymbolAddress((void**)&V, g_V);
    cudaGetSymbolAddress((void**)&C, g_C);
    cudaGetSymbolAddress((void**)&Xr, g_Xr);

    // 0: rope table
    rope_table_kernel<<<(S_LEN * 32 + 255) / 256, 256>>>();

    // 1: pre-round x + weights
    int nr4 = (NTOK * D_MODEL + 4 * D_MODEL * D_MODEL) / 4;
    preround_kernel<<<(nr4 + 255) / 256, 256>>>(x, Wq, Wk, Wv, Wo);

    // 2: fused QKV projections + RoPE epilogue (tf32-rounded outputs)
    qkv_gemm_kernel<<<dim3(D_MODEL / 128, NTOK / 128, 3), 256>>>(Xr);

    // 3: attention
    cudaFuncSetAttribute(attn_tf32, cudaFuncAttributeMaxDynamicSharedMemorySize, ATT_SMEM2);
    attn_tf32<<<dim3(S_LEN / 128, N_HEADS, BATCH), 256, ATT_SMEM2>>>(Q, K, V, C);

    // 4: output projection
    out_gemm_kernel<<<dim3(D_MODEL / 128, NTOK / 128), 256>>>(out);
}

// round 7
// speedup vs baseline: 1.2943x; 1.1143x over previous
#include <cuda_runtime.h>
#include <math.h>

#define S_LEN    2048
#define D_MODEL  1024
#define N_HEADS  16
#define HEAD_DIM 64
#define BATCH    2
#define NTOK     (BATCH * S_LEN)   // 4096

// -------- scratch (device globals: no allocations allowed) --------
__device__ float g_Q[NTOK * D_MODEL];
__device__ float g_K[NTOK * D_MODEL];
__device__ float g_V[NTOK * D_MODEL];
__device__ float g_C[NTOK * D_MODEL];
__device__ float g_Xr[NTOK * D_MODEL];            // tf32-rounded x
__device__ float g_Wr[4][D_MODEL * D_MODEL];      // tf32-rounded Wq,Wk,Wv,Wo
__device__ float g_cos[S_LEN * 32];
__device__ float g_sin[S_LEN * 32];

#define LOG2E 1.4426950408889634f

__device__ __forceinline__ unsigned f2tf(float x) {
    unsigned u;
    asm("cvt.rna.tf32.f32 %0, %1;" : "=r"(u) : "f"(x));
    return u;
}
__device__ __forceinline__ float f2tff(float x) { return __uint_as_float(f2tf(x)); }

__device__ __forceinline__ void mma8(float c[4], const unsigned a[4],
                                     unsigned b0, unsigned b1) {
    asm volatile(
        "mma.sync.aligned.m16n8k8.row.col.f32.tf32.tf32.f32 "
        "{%0,%1,%2,%3},{%4,%5,%6,%7},{%8,%9},{%0,%1,%2,%3};"
        : "+f"(c[0]), "+f"(c[1]), "+f"(c[2]), "+f"(c[3])
        : "r"(a[0]), "r"(a[1]), "r"(a[2]), "r"(a[3]), "r"(b0), "r"(b1));
}

// =================================================================
// Pre-round x and the four weights to tf32-valued fp32 (one pass).
// =================================================================
__global__ void preround_kernel(const float* __restrict__ x,
                                const float* __restrict__ Wq,
                                const float* __restrict__ Wk,
                                const float* __restrict__ Wv,
                                const float* __restrict__ Wo)
{
    const int NX = NTOK * D_MODEL / 4;
    const int NW = D_MODEL * D_MODEL / 4;
    int i = blockIdx.x * blockDim.x + threadIdx.x;
    const float4* src;
    float4* dst;
    if (i < NX) { src = (const float4*)x; dst = (float4*)g_Xr; }
    else {
        int j = i - NX;
        int w = j / NW;
        i = j - w * NW;
        const float* ws[4] = {Wq, Wk, Wv, Wo};
        src = (const float4*)ws[w];
        dst = (float4*)g_Wr[w];
    }
    float4 v = src[i];
    v.x = f2tff(v.x); v.y = f2tff(v.y); v.z = f2tff(v.z); v.w = f2tff(v.w);
    dst[i] = v;
}

// =================================================================
// RoPE table (fp32 angle matching jnp, fp64 sincos)
// =================================================================
__global__ void rope_table_kernel()
{
    int i = blockIdx.x * blockDim.x + threadIdx.x;
    if (i >= S_LEN * 32) return;
    int pos = i >> 5;
    int f   = i & 31;
    float e    = (float)(2 * f) / 64.0f;
    float pw   = powf(10000.0f, e);
    float invf = 1.0f / pw;
    float angf = (float)pos * invf;
    double s, c;
    sincos((double)angf, &s, &c);
    g_cos[i] = (float)c;
    g_sin[i] = (float)s;
}

// =================================================================
// TF32 GEMM core: C[M,N] = A[M,K] @ B[N,K]^T, inputs pre-rounded.
// 128x128x16 tile, 256 thr, 3-stage cp.async, ONE sync per iter.
// =================================================================
#define AST 20

__device__ __forceinline__ void gemm_body(
    const float* __restrict__ A, const float* __restrict__ B,
    float* __restrict__ C, int M, int N, int K,
    int mb, int nb, int rope_mode, float scale, int round_out)
{
    __shared__ __align__(16) float As[3][128 * AST];
    __shared__ __align__(16) float Bs[3][128 * AST];

    const int t    = threadIdx.x;
    const int warp = t >> 5, lane = t & 31;
    const int g    = lane >> 2, tig = lane & 3;
    const int wm   = (warp >> 2) * 64;
    const int wn   = (warp & 3) * 32;

    float acc[4][4][4];
#pragma unroll
    for (int mt = 0; mt < 4; mt++)
#pragma unroll
        for (int nt = 0; nt < 4; nt++)
#pragma unroll
            for (int i = 0; i < 4; i++) acc[mt][nt][i] = 0.f;

    const int lrow = t >> 2, lcol = (t & 3) * 4;

#define LOAD_STAGE3(buf, kt)                                                       \
    do {                                                                           \
        unsigned da = (unsigned)__cvta_generic_to_shared(                          \
            &As[buf][lrow * AST + lcol]);                                          \
        const float* ga = A + (size_t)(mb + lrow) * K + (kt) + lcol;               \
        asm volatile("cp.async.cg.shared.global [%0], [%1], 16;"                   \
                     :: "r"(da), "l"(ga));                                         \
        unsigned db = (unsigned)__cvta_generic_to_shared(                          \
            &Bs[buf][lrow * AST + lcol]);                                          \
        const float* gb = B + (size_t)(nb + lrow) * K + (kt) + lcol;               \
        asm volatile("cp.async.cg.shared.global [%0], [%1], 16;"                   \
                     :: "r"(db), "l"(gb));                                         \
        unsigned da2 = (unsigned)__cvta_generic_to_shared(                         \
            &As[buf][(lrow + 64) * AST + lcol]);                                   \
        const float* ga2 = A + (size_t)(mb + lrow + 64) * K + (kt) + lcol;         \
        asm volatile("cp.async.cg.shared.global [%0], [%1], 16;"                   \
                     :: "r"(da2), "l"(ga2));                                       \
        unsigned db2 = (unsigned)__cvta_generic_to_shared(                         \
            &Bs[buf][(lrow + 64) * AST + lcol]);                                   \
        const float* gb2 = B + (size_t)(nb + lrow + 64) * K + (kt) + lcol;         \
        asm volatile("cp.async.cg.shared.global [%0], [%1], 16;"                   \
                     :: "r"(db2), "l"(gb2));                                       \
        asm volatile("cp.async.commit_group;");                                    \
    } while (0)

    const int NIT = K / 16;
    LOAD_STAGE3(0, 0);
    LOAD_STAGE3(1, 16);

    for (int i = 0; i < NIT; i++) {
        asm volatile("cp.async.wait_group 1;");
        __syncthreads();
        if (i + 2 < NIT) {
            int nbuf = (i + 2) % 3;
            LOAD_STAGE3(nbuf, (i + 2) * 16);
        }
        const float* Ab = As[i % 3];
        const float* Bb = Bs[i % 3];

#pragma unroll
        for (int ks = 0; ks < 2; ks++) {
            const int kb = ks * 8;
            unsigned af[4][4], bf[4][2];
#pragma unroll
            for (int mt = 0; mt < 4; mt++) {
                int r0 = wm + mt * 16 + g;
                af[mt][0] = __float_as_uint(Ab[r0 * AST + kb + tig]);
                af[mt][1] = __float_as_uint(Ab[(r0 + 8) * AST + kb + tig]);
                af[mt][2] = __float_as_uint(Ab[r0 * AST + kb + tig + 4]);
                af[mt][3] = __float_as_uint(Ab[(r0 + 8) * AST + kb + tig + 4]);
            }
#pragma unroll
            for (int nt = 0; nt < 4; nt++) {
                int n0 = wn + nt * 8 + g;
                bf[nt][0] = __float_as_uint(Bb[n0 * AST + kb + tig]);
                bf[nt][1] = __float_as_uint(Bb[n0 * AST + kb + tig + 4]);
            }
#pragma unroll
            for (int mt = 0; mt < 4; mt++)
#pragma unroll
                for (int nt = 0; nt < 4; nt++)
                    mma8(acc[mt][nt], af[mt], bf[nt][0], bf[nt][1]);
        }
    }

    // ---- epilogue (optional fused RoPE, optional tf32 rounding) ----
#pragma unroll
    for (int mt = 0; mt < 4; mt++) {
#pragma unroll
        for (int nt = 0; nt < 4; nt++) {
            int row = mb + wm + mt * 16 + g;
            int col = nb + wn + nt * 8 + 2 * tig;
            float v0 = acc[mt][nt][0], v1 = acc[mt][nt][1];
            float v2 = acc[mt][nt][2], v3 = acc[mt][nt][3];
            if (rope_mode) {
                int fi = (col & 63) >> 1;
                int p0 = row & (S_LEN - 1);
                int p1 = (row + 8) & (S_LEN - 1);
                float c0 = g_cos[p0 * 32 + fi], s0 = g_sin[p0 * 32 + fi];
                float c1 = g_cos[p1 * 32 + fi], s1 = g_sin[p1 * 32 + fi];
                float r0 = v0 * c0 - v1 * s0, r1 = v0 * s0 + v1 * c0;
                float r2 = v2 * c1 - v3 * s1, r3 = v2 * s1 + v3 * c1;
                v0 = r0 * scale; v1 = r1 * scale;
                v2 = r2 * scale; v3 = r3 * scale;
            }
            if (round_out) {
                v0 = f2tff(v0); v1 = f2tff(v1);
                v2 = f2tff(v2); v3 = f2tff(v3);
            }
            *(float2*)&C[(size_t)row * N + col] = make_float2(v0, v1);
            *(float2*)&C[(size_t)(row + 8) * N + col] = make_float2(v2, v3);
        }
    }
}

__global__ __launch_bounds__(256, 2) void qkv_gemm_kernel(const float* __restrict__ A)
{
    const int z = blockIdx.z;
    float* outs[3] = {g_Q, g_K, g_V};
    const float* B = g_Wr[z];
    float* C = outs[z];
    int rope_mode = (z < 2) ? 1 : 0;
    float scale = (z == 0) ? 0.125f * LOG2E : 1.0f;  // fold 1/sqrt(hd) + log2e into Q
    gemm_body(A, B, C, NTOK, D_MODEL, D_MODEL,
              blockIdx.y * 128, blockIdx.x * 128, rope_mode, scale, 1);
}

__global__ __launch_bounds__(256, 2) void out_gemm_kernel(float* __restrict__ out)
{
    gemm_body(g_C, g_Wr[3], out, NTOK, D_MODEL, D_MODEL,
              blockIdx.y * 128, blockIdx.x * 128, 0, 1.0f, 0);
}

// =================================================================
// TF32 flash attention, causal. 128 threads = 4 warps, 32 q-rows/warp.
// B-fragments (K,V) loaded once per warp feed TWO 16-row mma blocks:
// halves smem crossbar traffic vs 8-warp/16-row version.
// Strides: Ks=68 (K-frag reads conflict-free: 4g+tig), Vs=72 (8tig+g),
// Ps=68 (qf/pf reads conflict-free).
// =================================================================
#define KST 68
#define VST 72
#define PST 68
#define KS_OFF 0
#define VS_OFF (64 * KST)
#define PS_OFF (64 * KST + 64 * VST)
#define ATT_SMEM3 ((64 * KST + 64 * VST + 128 * PST) * (int)sizeof(float))

__global__ __launch_bounds__(128, 2) void attn_tf32(
    const float* __restrict__ Q, const float* __restrict__ K,
    const float* __restrict__ V, float* __restrict__ Ctx)
{
    extern __shared__ __align__(16) float sm3[];
    float* Ks = sm3 + KS_OFF;
    float* Vs = sm3 + VS_OFF;
    float* Ps = sm3 + PS_OFF;

    const int t = threadIdx.x, warp = t >> 5, lane = t & 31;
    const int g = lane >> 2, tig = lane & 3;
    const int qb = ((int)gridDim.x - 1 - (int)blockIdx.x) * 128;  // heavy tiles first
    const int h  = blockIdx.y, b = blockIdx.z;
    const int w32 = warp * 32;

    const float* Qg = Q + ((size_t)b * S_LEN + qb) * D_MODEL + h * HEAD_DIM;

    // ---- stage Q (pre-rounded tf32) into Ps rows ----
#pragma unroll
    for (int i = 0; i < 16; i++) {
        int idx = t + i * 128;
        int row = idx >> 4, c4 = (idx & 15) * 4;
        *(float4*)&Ps[row * PST + c4] =
            *(const float4*)&Qg[(size_t)row * D_MODEL + c4];
    }
    __syncthreads();

    // ---- Q A-fragments for both 16-row blocks ----
    unsigned qf[2][8][4];
#pragma unroll
    for (int bb = 0; bb < 2; bb++)
#pragma unroll
        for (int kc = 0; kc < 8; kc++) {
            int rr = w32 + bb * 16 + g;
            qf[bb][kc][0] = __float_as_uint(Ps[rr * PST + kc * 8 + tig]);
            qf[bb][kc][1] = __float_as_uint(Ps[(rr + 8) * PST + kc * 8 + tig]);
            qf[bb][kc][2] = __float_as_uint(Ps[rr * PST + kc * 8 + tig + 4]);
            qf[bb][kc][3] = __float_as_uint(Ps[(rr + 8) * PST + kc * 8 + tig + 4]);
        }

    float m_[2][2], l_[2][2];
    float o[2][8][4];
#pragma unroll
    for (int bb = 0; bb < 2; bb++) {
        m_[bb][0] = -1e30f; m_[bb][1] = -1e30f;
        l_[bb][0] = 0.f;    l_[bb][1] = 0.f;
#pragma unroll
        for (int nt = 0; nt < 8; nt++)
#pragma unroll
            for (int i = 0; i < 4; i++) o[bb][nt][i] = 0.f;
    }

    const int wrow_max = qb + w32 + 31;

    for (int kt = 0; kt <= qb + 64; kt += 64) {
        __syncthreads();   // prev-iter Ks/Vs/Ps reads complete
        const float* Kg = K + ((size_t)b * S_LEN + kt) * D_MODEL + h * HEAD_DIM;
        const float* Vg = V + ((size_t)b * S_LEN + kt) * D_MODEL + h * HEAD_DIM;
#pragma unroll
        for (int i = 0; i < 8; i++) {
            int idx = t + i * 128;
            int row = idx >> 4, c4 = (idx & 15) * 4;
            *(float4*)&Ks[row * KST + c4] =
                *(const float4*)&Kg[(size_t)row * D_MODEL + c4];
            *(float4*)&Vs[row * VST + c4] =
                *(const float4*)&Vg[(size_t)row * D_MODEL + c4];
        }
        __syncthreads();

        if (kt > wrow_max) continue;

        // ---- S = Q K^T for both blocks; K B-frags loaded ONCE ----
        float s[2][8][4];
#pragma unroll
        for (int nt = 0; nt < 8; nt++) {
            float c0[4] = {0.f, 0.f, 0.f, 0.f};
            float c1[4] = {0.f, 0.f, 0.f, 0.f};
#pragma unroll
            for (int kc = 0; kc < 8; kc++) {
                unsigned b0 = __float_as_uint(Ks[(nt * 8 + g) * KST + kc * 8 + tig]);
                unsigned b1 = __float_as_uint(Ks[(nt * 8 + g) * KST + kc * 8 + tig + 4]);
                mma8(c0, qf[0][kc], b0, b1);
                mma8(c1, qf[1][kc], b0, b1);
            }
#pragma unroll
            for (int i = 0; i < 4; i++) { s[0][nt][i] = c0[i]; s[1][nt][i] = c1[i]; }
        }

        // ---- causal mask + online softmax per block ----
#pragma unroll
        for (int bb = 0; bb < 2; bb++) {
            const int r0 = qb + w32 + bb * 16 + g;
            const int r1 = r0 + 8;
            if (kt + 63 > qb + w32 + bb * 16) {
#pragma unroll
                for (int nt = 0; nt < 8; nt++) {
                    int k0 = kt + nt * 8 + 2 * tig;
                    if (k0 > r0)     s[bb][nt][0] = -1e30f;
                    if (k0 + 1 > r0) s[bb][nt][1] = -1e30f;
                    if (k0 > r1)     s[bb][nt][2] = -1e30f;
                    if (k0 + 1 > r1) s[bb][nt][3] = -1e30f;
                }
            }

            float mx0 = -1e30f, mx1 = -1e30f;
#pragma unroll
            for (int nt = 0; nt < 8; nt++) {
                mx0 = fmaxf(mx0, fmaxf(s[bb][nt][0], s[bb][nt][1]));
                mx1 = fmaxf(mx1, fmaxf(s[bb][nt][2], s[bb][nt][3]));
            }
            mx0 = fmaxf(mx0, __shfl_xor_sync(0xffffffffu, mx0, 1));
            mx0 = fmaxf(mx0, __shfl_xor_sync(0xffffffffu, mx0, 2));
            mx1 = fmaxf(mx1, __shfl_xor_sync(0xffffffffu, mx1, 1));
            mx1 = fmaxf(mx1, __shfl_xor_sync(0xffffffffu, mx1, 2));

            float nm0 = fmaxf(m_[bb][0], mx0), nm1 = fmaxf(m_[bb][1], mx1);
            float a0 = exp2f(m_[bb][0] - nm0), a1 = exp2f(m_[bb][1] - nm1);
            float sum0 = 0.f, sum1 = 0.f;
#pragma unroll
            for (int nt = 0; nt < 8; nt++) {
                s[bb][nt][0] = exp2f(s[bb][nt][0] - nm0);
                s[bb][nt][1] = exp2f(s[bb][nt][1] - nm0);
                s[bb][nt][2] = exp2f(s[bb][nt][2] - nm1);
                s[bb][nt][3] = exp2f(s[bb][nt][3] - nm1);
                sum0 += s[bb][nt][0] + s[bb][nt][1];
                sum1 += s[bb][nt][2] + s[bb][nt][3];
            }
            sum0 += __shfl_xor_sync(0xffffffffu, sum0, 1);
            sum0 += __shfl_xor_sync(0xffffffffu, sum0, 2);
            sum1 += __shfl_xor_sync(0xffffffffu, sum1, 1);
            sum1 += __shfl_xor_sync(0xffffffffu, sum1, 2);

            l_[bb][0] = l_[bb][0] * a0 + sum0;
            l_[bb][1] = l_[bb][1] * a1 + sum1;
            m_[bb][0] = nm0; m_[bb][1] = nm1;
#pragma unroll
            for (int nt = 0; nt < 8; nt++) {
                o[bb][nt][0] *= a0; o[bb][nt][1] *= a0;
                o[bb][nt][2] *= a1; o[bb][nt][3] *= a1;
            }

            // P (tf32) to warp-private Ps rows
#pragma unroll
            for (int nt = 0; nt < 8; nt++) {
                *(float2*)&Ps[(w32 + bb * 16 + g) * PST + nt * 8 + 2 * tig] =
                    make_float2(f2tff(s[bb][nt][0]), f2tff(s[bb][nt][1]));
                *(float2*)&Ps[(w32 + bb * 16 + g + 8) * PST + nt * 8 + 2 * tig] =
                    make_float2(f2tff(s[bb][nt][2]), f2tff(s[bb][nt][3]));
            }
        }
        __syncwarp();

        // ---- O += P @ V; V B-frags loaded ONCE feed both blocks ----
#pragma unroll
        for (int kc = 0; kc < 8; kc++) {
            unsigned pf[2][4];
#pragma unroll
            for (int bb = 0; bb < 2; bb++) {
                int rr = w32 + bb * 16 + g;
                pf[bb][0] = __float_as_uint(Ps[rr * PST + kc * 8 + tig]);
                pf[bb][1] = __float_as_uint(Ps[(rr + 8) * PST + kc * 8 + tig]);
                pf[bb][2] = __float_as_uint(Ps[rr * PST + kc * 8 + tig + 4]);
                pf[bb][3] = __float_as_uint(Ps[(rr + 8) * PST + kc * 8 + tig + 4]);
            }
#pragma unroll
            for (int nt = 0; nt < 8; nt++) {
                unsigned b0 = __float_as_uint(Vs[(kc * 8 + tig) * VST + nt * 8 + g]);
                unsigned b1 = __float_as_uint(Vs[(kc * 8 + tig + 4) * VST + nt * 8 + g]);
                mma8(o[0][nt], pf[0], b0, b1);
                mma8(o[1][nt], pf[1], b0, b1);
            }
        }
        __syncwarp();   // Ps reads done before next iteration's stores
    }

    // ---- epilogue: normalize, round to tf32 (next GEMM input), store ----
#pragma unroll
    for (int bb = 0; bb < 2; bb++) {
        float inv0 = 1.0f / l_[bb][0], inv1 = 1.0f / l_[bb][1];
        float* Cb = Ctx + ((size_t)b * S_LEN + qb + w32 + bb * 16) * D_MODEL
                        + h * HEAD_DIM;
#pragma unroll
        for (int nt = 0; nt < 8; nt++) {
            *(float2*)&Cb[(size_t)g * D_MODEL + nt * 8 + 2 * tig] =
                make_float2(f2tff(o[bb][nt][0] * inv0), f2tff(o[bb][nt][1] * inv0));
            *(float2*)&Cb[(size_t)(g + 8) * D_MODEL + nt * 8 + 2 * tig] =
                make_float2(f2tff(o[bb][nt][2] * inv1), f2tff(o[bb][nt][3] * inv1));
        }
    }
}

// =================================================================
// Launch
// =================================================================
extern "C" void kernel_launch(void* const* d_in, const int* in_sizes, int n_in,
                              void* d_out, int out_size)
{
    const float* x  = (const float*)d_in[0];
    const float* Wq = (const float*)d_in[1];
    const float* Wk = (const float*)d_in[2];
    const float* Wv = (const float*)d_in[3];
    const float* Wo = (const float*)d_in[4];
    float* out = (float*)d_out;

    float *Q, *K, *V, *C, *Xr;
    cudaGetSymbolAddress((void**)&Q, g_Q);
    cudaGetSymbolAddress((void**)&K, g_K);
    cudaGetSymbolAddress((void**)&V, g_V);
    cudaGetSymbolAddress((void**)&C, g_C);
    cudaGetSymbolAddress((void**)&Xr, g_Xr);

    // 0: rope table
    rope_table_kernel<<<(S_LEN * 32 + 255) / 256, 256>>>();

    // 1: pre-round x + weights
    int nr4 = (NTOK * D_MODEL + 4 * D_MODEL * D_MODEL) / 4;
    preround_kernel<<<(nr4 + 255) / 256, 256>>>(x, Wq, Wk, Wv, Wo);

    // 2: fused QKV projections + RoPE epilogue (tf32-rounded outputs)
    qkv_gemm_kernel<<<dim3(D_MODEL / 128, NTOK / 128, 3), 256>>>(Xr);

    // 3: attention (4 warps x 32 rows)
    cudaFuncSetAttribute(attn_tf32, cudaFuncAttributeMaxDynamicSharedMemorySize, ATT_SMEM3);
    attn_tf32<<<dim3(S_LEN / 128, N_HEADS, BATCH), 128, ATT_SMEM3>>>(Q, K, V, C);

    // 4: output projection
    out_gemm_kernel<<<dim3(D_MODEL / 128, NTOK / 128), 256>>>(out);
}

// round 8
// speedup vs baseline: 1.3423x; 1.0371x over previous
#include <cuda_runtime.h>
#include <math.h>

#define S_LEN    2048
#define D_MODEL  1024
#define N_HEADS  16
#define HEAD_DIM 64
#define BATCH    2
#define NTOK     (BATCH * S_LEN)   // 4096

// -------- scratch (device globals: no allocations allowed) --------
__device__ float g_Q[NTOK * D_MODEL];
__device__ float g_K[NTOK * D_MODEL];
__device__ float g_V[NTOK * D_MODEL];
__device__ float g_C[NTOK * D_MODEL];
__device__ float g_Xr[NTOK * D_MODEL];            // tf32-rounded x
__device__ float g_Wr[4][D_MODEL * D_MODEL];      // tf32-rounded Wq,Wk,Wv,Wo
__device__ float g_cos[S_LEN * 32];
__device__ float g_sin[S_LEN * 32];

#define LOG2E 1.4426950408889634f

__device__ __forceinline__ unsigned f2tf(float x) {
    unsigned u;
    asm("cvt.rna.tf32.f32 %0, %1;" : "=r"(u) : "f"(x));
    return u;
}
__device__ __forceinline__ float f2tff(float x) { return __uint_as_float(f2tf(x)); }

__device__ __forceinline__ void mma8(float c[4], const unsigned a[4],
                                     unsigned b0, unsigned b1) {
    asm volatile(
        "mma.sync.aligned.m16n8k8.row.col.f32.tf32.tf32.f32 "
        "{%0,%1,%2,%3},{%4,%5,%6,%7},{%8,%9},{%0,%1,%2,%3};"
        : "+f"(c[0]), "+f"(c[1]), "+f"(c[2]), "+f"(c[3])
        : "r"(a[0]), "r"(a[1]), "r"(a[2]), "r"(a[3]), "r"(b0), "r"(b1));
}

// =================================================================
// Pre-round x and the four weights to tf32-valued fp32 (one pass).
// =================================================================
__global__ void preround_kernel(const float* __restrict__ x,
                                const float* __restrict__ Wq,
                                const float* __restrict__ Wk,
                                const float* __restrict__ Wv,
                                const float* __restrict__ Wo)
{
    const int NX = NTOK * D_MODEL / 4;
    const int NW = D_MODEL * D_MODEL / 4;
    int i = blockIdx.x * blockDim.x + threadIdx.x;
    const float4* src;
    float4* dst;
    if (i < NX) { src = (const float4*)x; dst = (float4*)g_Xr; }
    else {
        int j = i - NX;
        int w = j / NW;
        i = j - w * NW;
        const float* ws[4] = {Wq, Wk, Wv, Wo};
        src = (const float4*)ws[w];
        dst = (float4*)g_Wr[w];
    }
    float4 v = src[i];
    v.x = f2tff(v.x); v.y = f2tff(v.y); v.z = f2tff(v.z); v.w = f2tff(v.w);
    dst[i] = v;
}

// =================================================================
// RoPE table (fp32 angle matching jnp, fp64 sincos)
// =================================================================
__global__ void rope_table_kernel()
{
    int i = blockIdx.x * blockDim.x + threadIdx.x;
    if (i >= S_LEN * 32) return;
    int pos = i >> 5;
    int f   = i & 31;
    float e    = (float)(2 * f) / 64.0f;
    float pw   = powf(10000.0f, e);
    float invf = 1.0f / pw;
    float angf = (float)pos * invf;
    double s, c;
    sincos((double)angf, &s, &c);
    g_cos[i] = (float)c;
    g_sin[i] = (float)s;
}

// =================================================================
// TF32 GEMM core: C[M,N] = A[M,K] @ B[N,K]^T, inputs pre-rounded.
// 128x128x16 CTA tile, 128 threads = 4 warps (2x2), 64x64 warp tile.
// Per warp k16-iter: 64 LDS.32 feed 64 mmas (LDS/mma = 1.0).
// 3-stage cp.async, ONE sync per iter. K-order per element unchanged
// vs previous version -> bit-identical output.
// =================================================================
#define AST 20

__device__ __forceinline__ void gemm_body(
    const float* __restrict__ A, const float* __restrict__ B,
    float* __restrict__ C, int M, int N, int K,
    int mb, int nb, int rope_mode, float scale, int round_out)
{
    __shared__ __align__(16) float As[3][128 * AST];
    __shared__ __align__(16) float Bs[3][128 * AST];

    const int t    = threadIdx.x;
    const int warp = t >> 5, lane = t & 31;
    const int g    = lane >> 2, tig = lane & 3;
    const int wm   = (warp >> 1) * 64;   // 2x2 warp grid
    const int wn   = (warp & 1) * 64;

    float acc[4][8][4];
#pragma unroll
    for (int mt = 0; mt < 4; mt++)
#pragma unroll
        for (int nt = 0; nt < 8; nt++)
#pragma unroll
            for (int i = 0; i < 4; i++) acc[mt][nt][i] = 0.f;

    const int lrow = t >> 2, lcol = (t & 3) * 4;   // lrow 0..31

#define LOAD_STAGE3(buf, kt)                                                       \
    do {                                                                           \
        _Pragma("unroll")                                                          \
        for (int rr = 0; rr < 4; rr++) {                                           \
            int row = lrow + rr * 32;                                              \
            unsigned da = (unsigned)__cvta_generic_to_shared(                      \
                &As[buf][row * AST + lcol]);                                       \
            const float* ga = A + (size_t)(mb + row) * K + (kt) + lcol;            \
            asm volatile("cp.async.cg.shared.global [%0], [%1], 16;"               \
                         :: "r"(da), "l"(ga));                                     \
            unsigned db = (unsigned)__cvta_generic_to_shared(                      \
                &Bs[buf][row * AST + lcol]);                                       \
            const float* gb = B + (size_t)(nb + row) * K + (kt) + lcol;            \
            asm volatile("cp.async.cg.shared.global [%0], [%1], 16;"               \
                         :: "r"(db), "l"(gb));                                     \
        }                                                                          \
        asm volatile("cp.async.commit_group;");                                    \
    } while (0)

    const int NIT = K / 16;
    LOAD_STAGE3(0, 0);
    LOAD_STAGE3(1, 16);

    for (int i = 0; i < NIT; i++) {
        asm volatile("cp.async.wait_group 1;");
        __syncthreads();
        if (i + 2 < NIT) {
            int nbuf = (i + 2) % 3;
            LOAD_STAGE3(nbuf, (i + 2) * 16);
        }
        const float* Ab = As[i % 3];
        const float* Bb = Bs[i % 3];

#pragma unroll
        for (int ks = 0; ks < 2; ks++) {
            const int kb = ks * 8;
            unsigned af[4][4], bf[8][2];
#pragma unroll
            for (int mt = 0; mt < 4; mt++) {
                int r0 = wm + mt * 16 + g;
                af[mt][0] = __float_as_uint(Ab[r0 * AST + kb + tig]);
                af[mt][1] = __float_as_uint(Ab[(r0 + 8) * AST + kb + tig]);
                af[mt][2] = __float_as_uint(Ab[r0 * AST + kb + tig + 4]);
                af[mt][3] = __float_as_uint(Ab[(r0 + 8) * AST + kb + tig + 4]);
            }
#pragma unroll
            for (int nt = 0; nt < 8; nt++) {
                int n0 = wn + nt * 8 + g;
                bf[nt][0] = __float_as_uint(Bb[n0 * AST + kb + tig]);
                bf[nt][1] = __float_as_uint(Bb[n0 * AST + kb + tig + 4]);
            }
#pragma unroll
            for (int mt = 0; mt < 4; mt++)
#pragma unroll
                for (int nt = 0; nt < 8; nt++)
                    mma8(acc[mt][nt], af[mt], bf[nt][0], bf[nt][1]);
        }
    }

    // ---- epilogue (optional fused RoPE, optional tf32 rounding) ----
#pragma unroll
    for (int mt = 0; mt < 4; mt++) {
#pragma unroll
        for (int nt = 0; nt < 8; nt++) {
            int row = mb + wm + mt * 16 + g;
            int col = nb + wn + nt * 8 + 2 * tig;
            float v0 = acc[mt][nt][0], v1 = acc[mt][nt][1];
            float v2 = acc[mt][nt][2], v3 = acc[mt][nt][3];
            if (rope_mode) {
                int fi = (col & 63) >> 1;
                int p0 = row & (S_LEN - 1);
                int p1 = (row + 8) & (S_LEN - 1);
                float c0 = g_cos[p0 * 32 + fi], s0 = g_sin[p0 * 32 + fi];
                float c1 = g_cos[p1 * 32 + fi], s1 = g_sin[p1 * 32 + fi];
                float r0 = v0 * c0 - v1 * s0, r1 = v0 * s0 + v1 * c0;
                float r2 = v2 * c1 - v3 * s1, r3 = v2 * s1 + v3 * c1;
                v0 = r0 * scale; v1 = r1 * scale;
                v2 = r2 * scale; v3 = r3 * scale;
            }
            if (round_out) {
                v0 = f2tff(v0); v1 = f2tff(v1);
                v2 = f2tff(v2); v3 = f2tff(v3);
            }
            *(float2*)&C[(size_t)row * N + col] = make_float2(v0, v1);
            *(float2*)&C[(size_t)(row + 8) * N + col] = make_float2(v2, v3);
        }
    }
}

__global__ __launch_bounds__(128, 2) void qkv_gemm_kernel(const float* __restrict__ A)
{
    const int z = blockIdx.z;
    float* outs[3] = {g_Q, g_K, g_V};
    const float* B = g_Wr[z];
    float* C = outs[z];
    int rope_mode = (z < 2) ? 1 : 0;
    float scale = (z == 0) ? 0.125f * LOG2E : 1.0f;  // fold 1/sqrt(hd) + log2e into Q
    gemm_body(A, B, C, NTOK, D_MODEL, D_MODEL,
              blockIdx.y * 128, blockIdx.x * 128, rope_mode, scale, 1);
}

__global__ __launch_bounds__(128, 2) void out_gemm_kernel(float* __restrict__ out)
{
    gemm_body(g_C, g_Wr[3], out, NTOK, D_MODEL, D_MODEL,
              blockIdx.y * 128, blockIdx.x * 128, 0, 1.0f, 0);
}

// =================================================================
// TF32 flash attention, causal. 128 threads = 4 warps, 32 q-rows/warp.
// (unchanged from R7 best: 171us)
// =================================================================
#define KST 68
#define VST 72
#define PST 68
#define KS_OFF 0
#define VS_OFF (64 * KST)
#define PS_OFF (64 * KST + 64 * VST)
#define ATT_SMEM3 ((64 * KST + 64 * VST + 128 * PST) * (int)sizeof(float))

__global__ __launch_bounds__(128, 2) void attn_tf32(
    const float* __restrict__ Q, const float* __restrict__ K,
    const float* __restrict__ V, float* __restrict__ Ctx)
{
    extern __shared__ __align__(16) float sm3[];
    float* Ks = sm3 + KS_OFF;
    float* Vs = sm3 + VS_OFF;
    float* Ps = sm3 + PS_OFF;

    const int t = threadIdx.x, warp = t >> 5, lane = t & 31;
    const int g = lane >> 2, tig = lane & 3;
    const int qb = ((int)gridDim.x - 1 - (int)blockIdx.x) * 128;  // heavy tiles first
    const int h  = blockIdx.y, b = blockIdx.z;
    const int w32 = warp * 32;

    const float* Qg = Q + ((size_t)b * S_LEN + qb) * D_MODEL + h * HEAD_DIM;

    // ---- stage Q (pre-rounded tf32) into Ps rows ----
#pragma unroll
    for (int i = 0; i < 16; i++) {
        int idx = t + i * 128;
        int row = idx >> 4, c4 = (idx & 15) * 4;
        *(float4*)&Ps[row * PST + c4] =
            *(const float4*)&Qg[(size_t)row * D_MODEL + c4];
    }
    __syncthreads();

    // ---- Q A-fragments for both 16-row blocks ----
    unsigned qf[2][8][4];
#pragma unroll
    for (int bb = 0; bb < 2; bb++)
#pragma unroll
        for (int kc = 0; kc < 8; kc++) {
            int rr = w32 + bb * 16 + g;
            qf[bb][kc][0] = __float_as_uint(Ps[rr * PST + kc * 8 + tig]);
            qf[bb][kc][1] = __float_as_uint(Ps[(rr + 8) * PST + kc * 8 + tig]);
            qf[bb][kc][2] = __float_as_uint(Ps[rr * PST + kc * 8 + tig + 4]);
            qf[bb][kc][3] = __float_as_uint(Ps[(rr + 8) * PST + kc * 8 + tig + 4]);
        }

    float m_[2][2], l_[2][2];
    float o[2][8][4];
#pragma unroll
    for (int bb = 0; bb < 2; bb++) {
        m_[bb][0] = -1e30f; m_[bb][1] = -1e30f;
        l_[bb][0] = 0.f;    l_[bb][1] = 0.f;
#pragma unroll
        for (int nt = 0; nt < 8; nt++)
#pragma unroll
            for (int i = 0; i < 4; i++) o[bb][nt][i] = 0.f;
    }

    const int wrow_max = qb + w32 + 31;

    for (int kt = 0; kt <= qb + 64; kt += 64) {
        __syncthreads();   // prev-iter Ks/Vs/Ps reads complete
        const float* Kg = K + ((size_t)b * S_LEN + kt) * D_MODEL + h * HEAD_DIM;
        const float* Vg = V + ((size_t)b * S_LEN + kt) * D_MODEL + h * HEAD_DIM;
#pragma unroll
        for (int i = 0; i < 8; i++) {
            int idx = t + i * 128;
            int row = idx >> 4, c4 = (idx & 15) * 4;
            *(float4*)&Ks[row * KST + c4] =
                *(const float4*)&Kg[(size_t)row * D_MODEL + c4];
            *(float4*)&Vs[row * VST + c4] =
                *(const float4*)&Vg[(size_t)row * D_MODEL + c4];
        }
        __syncthreads();

        if (kt > wrow_max) continue;

        // ---- S = Q K^T for both blocks; K B-frags loaded ONCE ----
        float s[2][8][4];
#pragma unroll
        for (int nt = 0; nt < 8; nt++) {
            float c0[4] = {0.f, 0.f, 0.f, 0.f};
            float c1[4] = {0.f, 0.f, 0.f, 0.f};
#pragma unroll
            for (int kc = 0; kc < 8; kc++) {
                unsigned b0 = __float_as_uint(Ks[(nt * 8 + g) * KST + kc * 8 + tig]);
                unsigned b1 = __float_as_uint(Ks[(nt * 8 + g) * KST + kc * 8 + tig + 4]);
                mma8(c0, qf[0][kc], b0, b1);
                mma8(c1, qf[1][kc], b0, b1);
            }
#pragma unroll
            for (int i = 0; i < 4; i++) { s[0][nt][i] = c0[i]; s[1][nt][i] = c1[i]; }
        }

        // ---- causal mask + online softmax per block ----
#pragma unroll
        for (int bb = 0; bb < 2; bb++) {
            const int r0 = qb + w32 + bb * 16 + g;
            const int r1 = r0 + 8;
            if (kt + 63 > qb + w32 + bb * 16) {
#pragma unroll
                for (int nt = 0; nt < 8; nt++) {
                    int k0 = kt + nt * 8 + 2 * tig;
                    if (k0 > r0)     s[bb][nt][0] = -1e30f;
                    if (k0 + 1 > r0) s[bb][nt][1] = -1e30f;
                    if (k0 > r1)     s[bb][nt][2] = -1e30f;
                    if (k0 + 1 > r1) s[bb][nt][3] = -1e30f;
                }
            }

            float mx0 = -1e30f, mx1 = -1e30f;
#pragma unroll
            for (int nt = 0; nt < 8; nt++) {
                mx0 = fmaxf(mx0, fmaxf(s[bb][nt][0], s[bb][nt][1]));
                mx1 = fmaxf(mx1, fmaxf(s[bb][nt][2], s[bb][nt][3]));
            }
            mx0 = fmaxf(mx0, __shfl_xor_sync(0xffffffffu, mx0, 1));
            mx0 = fmaxf(mx0, __shfl_xor_sync(0xffffffffu, mx0, 2));
            mx1 = fmaxf(mx1, __shfl_xor_sync(0xffffffffu, mx1, 1));
            mx1 = fmaxf(mx1, __shfl_xor_sync(0xffffffffu, mx1, 2));

            float nm0 = fmaxf(m_[bb][0], mx0), nm1 = fmaxf(m_[bb][1], mx1);
            float a0 = exp2f(m_[bb][0] - nm0), a1 = exp2f(m_[bb][1] - nm1);
            float sum0 = 0.f, sum1 = 0.f;
#pragma unroll
            for (int nt = 0; nt < 8; nt++) {
                s[bb][nt][0] = exp2f(s[bb][nt][0] - nm0);
                s[bb][nt][1] = exp2f(s[bb][nt][1] - nm0);
                s[bb][nt][2] = exp2f(s[bb][nt][2] - nm1);
                s[bb][nt][3] = exp2f(s[bb][nt][3] - nm1);
                sum0 += s[bb][nt][0] + s[bb][nt][1];
                sum1 += s[bb][nt][2] + s[bb][nt][3];
            }
            sum0 += __shfl_xor_sync(0xffffffffu, sum0, 1);
            sum0 += __shfl_xor_sync(0xffffffffu, sum0, 2);
            sum1 += __shfl_xor_sync(0xffffffffu, sum1, 1);
            sum1 += __shfl_xor_sync(0xffffffffu, sum1, 2);

            l_[bb][0] = l_[bb][0] * a0 + sum0;
            l_[bb][1] = l_[bb][1] * a1 + sum1;
            m_[bb][0] = nm0; m_[bb][1] = nm1;
#pragma unroll
            for (int nt = 0; nt < 8; nt++) {
                o[bb][nt][0] *= a0; o[bb][nt][1] *= a0;
                o[bb][nt][2] *= a1; o[bb][nt][3] *= a1;
            }

            // P (tf32) to warp-private Ps rows
#pragma unroll
            for (int nt = 0; nt < 8; nt++) {
                *(float2*)&Ps[(w32 + bb * 16 + g) * PST + nt * 8 + 2 * tig] =
                    make_float2(f2tff(s[bb][nt][0]), f2tff(s[bb][nt][1]));
                *(float2*)&Ps[(w32 + bb * 16 + g + 8) * PST + nt * 8 + 2 * tig] =
                    make_float2(f2tff(s[bb][nt][2]), f2tff(s[bb][nt][3]));
            }
        }
        __syncwarp();

        // ---- O += P @ V; V B-frags loaded ONCE feed both blocks ----
#pragma unroll
        for (int kc = 0; kc < 8; kc++) {
            unsigned pf[2][4];
#pragma unroll
            for (int bb = 0; bb < 2; bb++) {
                int rr = w32 + bb * 16 + g;
                pf[bb][0] = __float_as_uint(Ps[rr * PST + kc * 8 + tig]);
                pf[bb][1] = __float_as_uint(Ps[(rr + 8) * PST + kc * 8 + tig]);
                pf[bb][2] = __float_as_uint(Ps[rr * PST + kc * 8 + tig + 4]);
                pf[bb][3] = __float_as_uint(Ps[(rr + 8) * PST + kc * 8 + tig + 4]);
            }
#pragma unroll
            for (int nt = 0; nt < 8; nt++) {
                unsigned b0 = __float_as_uint(Vs[(kc * 8 + tig) * VST + nt * 8 + g]);
                unsigned b1 = __float_as_uint(Vs[(kc * 8 + tig + 4) * VST + nt * 8 + g]);
                mma8(o[0][nt], pf[0], b0, b1);
                mma8(o[1][nt], pf[1], b0, b1);
            }
        }
        __syncwarp();   // Ps reads done before next iteration's stores
    }

    // ---- epilogue: normalize, round to tf32 (next GEMM input), store ----
#pragma unroll
    for (int bb = 0; bb < 2; bb++) {
        float inv0 = 1.0f / l_[bb][0], inv1 = 1.0f / l_[bb][1];
        float* Cb = Ctx + ((size_t)b * S_LEN + qb + w32 + bb * 16) * D_MODEL
                        + h * HEAD_DIM;
#pragma unroll
        for (int nt = 0; nt < 8; nt++) {
            *(float2*)&Cb[(size_t)g * D_MODEL + nt * 8 + 2 * tig] =
                make_float2(f2tff(o[bb][nt][0] * inv0), f2tff(o[bb][nt][1] * inv0));
            *(float2*)&Cb[(size_t)(g + 8) * D_MODEL + nt * 8 + 2 * tig] =
                make_float2(f2tff(o[bb][nt][2] * inv1), f2tff(o[bb][nt][3] * inv1));
        }
    }
}

// =================================================================
// Launch
// =================================================================
extern "C" void kernel_launch(void* const* d_in, const int* in_sizes, int n_in,
                              void* d_out, int out_size)
{
    const float* x  = (const float*)d_in[0];
    const float* Wq = (const float*)d_in[1];
    const float* Wk = (const float*)d_in[2];
    const float* Wv = (const float*)d_in[3];
    const float* Wo = (const float*)d_in[4];
    float* out = (float*)d_out;

    float *Q, *K, *V, *C, *Xr;
    cudaGetSymbolAddress((void**)&Q, g_Q);
    cudaGetSymbolAddress((void**)&K, g_K);
    cudaGetSymbolAddress((void**)&V, g_V);
    cudaGetSymbolAddress((void**)&C, g_C);
    cudaGetSymbolAddress((void**)&Xr, g_Xr);

    // 0: rope table
    rope_table_kernel<<<(S_LEN * 32 + 255) / 256, 256>>>();

    // 1: pre-round x + weights
    int nr4 = (NTOK * D_MODEL + 4 * D_MODEL * D_MODEL) / 4;
    preround_kernel<<<(nr4 + 255) / 256, 256>>>(x, Wq, Wk, Wv, Wo);

    // 2: fused QKV projections + RoPE epilogue (tf32-rounded outputs)
    qkv_gemm_kernel<<<dim3(D_MODEL / 128, NTOK / 128, 3), 128>>>(Xr);

    // 3: attention (4 warps x 32 rows)
    cudaFuncSetAttribute(attn_tf32, cudaFuncAttributeMaxDynamicSharedMemorySize, ATT_SMEM3);
    attn_tf32<<<dim3(S_LEN / 128, N_HEADS, BATCH), 128, ATT_SMEM3>>>(Q, K, V, C);

    // 4: output projection
    out_gemm_kernel<<<dim3(D_MODEL / 128, NTOK / 128), 128>>>(out);
}